// round 1
// baseline (speedup 1.0000x reference)
#include <cuda_runtime.h>
#include <math.h>
#include <stdint.h>

#define BATCH 8
#define NPTS 4096
#define SPTS 1024
#define D1 128
#define D2 256
#define INCH 384
#define OUTCH 256
#define NTOT (BATCH * NPTS)   // 32768
#define BN_EPS 1e-5f

// ---------------- scratch (device globals; no allocs allowed) ----------------
__device__ float g_Xin[INCH * NTOT];    // fused input, channel-major [384][32768]
__device__ float g_Z[OUTCH * NTOT];     // pre-BN GEMM output (reused per layer)
__device__ float g_A1[OUTCH * NTOT];    // layer-fuse activation (residual source)
__device__ float g_A2[OUTCH * NTOT];    // layer-1 activation
__device__ float g_mean[OUTCH];
__device__ float g_rstd[OUTCH];

// ---------------- packed f32x2 helpers (FFMA2 path, sm_103a) ----------------
#define DUP_F32X2(out, f) \
    asm("mov.b64 %0, {%1, %1};" : "=l"(out) : "f"(f))
#define FMA_F32X2(acc, a, b) \
    asm("fma.rn.f32x2 %0, %1, %2, %0;" : "+l"(acc) : "l"(a), "l"(b))
#define UNPACK_F32X2(lo, hi, in) \
    asm("mov.b64 {%0, %1}, %2;" : "=f"(lo), "=f"(hi) : "l"(in))

__device__ __forceinline__ float gelu_exact(float x) {
    return 0.5f * x * (1.0f + erff(x * 0.70710678118654752f));
}

// ---------------- kernel 1: 3-NN interpolation + concat -> g_Xin ----------------
__global__ __launch_bounds__(256) void interp_kernel(
    const float* __restrict__ xyz1,    // [B, N, 3]
    const float* __restrict__ xyz2,    // [B, S, 3]
    const float* __restrict__ points1, // [B, N, 128]
    const float* __restrict__ points2) // [B, S, 256]
{
    __shared__ float4 q[SPTS];   // (x, y, z, |q|^2)
    const int b = blockIdx.y;
    const int n = blockIdx.x * blockDim.x + threadIdx.x;

    for (int s = threadIdx.x; s < SPTS; s += blockDim.x) {
        const float* p = xyz2 + ((size_t)b * SPTS + s) * 3;
        float x = p[0], y = p[1], z = p[2];
        q[s] = make_float4(x, y, z, x * x + y * y + z * z);
    }
    __syncthreads();

    const float* p = xyz1 + ((size_t)b * NPTS + n) * 3;
    float px = p[0], py = p[1], pz = p[2];
    float rn = px * px + py * py + pz * pz;

    float d0 = 3.4e38f, d1 = 3.4e38f, d2 = 3.4e38f;
    int i0 = 0, i1 = 0, i2 = 0;
    #pragma unroll 4
    for (int s = 0; s < SPTS; s++) {
        float4 qq = q[s];
        // same expanded form as reference: |p|^2 - 2 p.q + |q|^2
        float d = rn - 2.0f * (px * qq.x + py * qq.y + pz * qq.z) + qq.w;
        if (d < d2) {
            if (d < d1) {
                if (d < d0) { d2 = d1; i2 = i1; d1 = d0; i1 = i0; d0 = d; i0 = s; }
                else        { d2 = d1; i2 = i1; d1 = d;  i1 = s; }
            } else          { d2 = d;  i2 = s; }
        }
    }

    float r0 = 1.0f / (d0 + 1e-8f);
    float r1 = 1.0f / (d1 + 1e-8f);
    float r2 = 1.0f / (d2 + 1e-8f);
    float rs = 1.0f / (r0 + r1 + r2);
    float w0 = r0 * rs, w1 = r1 * rs, w2 = r2 * rs;

    const int sample = b * NPTS + n;

    // points1 passthrough -> channels [0, 128)
    const float* p1 = points1 + ((size_t)b * NPTS + n) * D1;
    #pragma unroll 4
    for (int c = 0; c < D1; c++)
        g_Xin[c * NTOT + sample] = __ldg(p1 + c);

    // interpolated points2 -> channels [128, 384)
    const float* q0 = points2 + ((size_t)b * SPTS + i0) * D2;
    const float* q1 = points2 + ((size_t)b * SPTS + i1) * D2;
    const float* q2 = points2 + ((size_t)b * SPTS + i2) * D2;
    #pragma unroll 4
    for (int c = 0; c < D2; c++) {
        float v = w0 * __ldg(q0 + c) + w1 * __ldg(q1 + c) + w2 * __ldg(q2 + c);
        g_Xin[(D1 + c) * NTOT + sample] = v;
    }
}

// ---------------- kernel 2: tiled GEMM  Z[m][n] = W[m][:] . X[:][n] + bias[m] ----------------
// M = 256 (out ch), N = 32768 (samples), K templated (384 or 256).
// BM=64, BN=128, BK=16; 256 threads; per-thread 8x4 microtile via f32x2 pairs over m.
template <int K>
__global__ __launch_bounds__(256) void gemm_bias_kernel(
    const float* __restrict__ W,    // [M, K] row-major
    const float* __restrict__ bias, // [M]
    const float* __restrict__ X)    // [K, NTOT]
{
    constexpr int BM = 64, BN = 128, BK = 16;
    __shared__ float As[BK][BM];
    __shared__ float Bs[BK][BN];

    const int t = threadIdx.x;
    const int n0 = blockIdx.x * BN;
    const int m0 = blockIdx.y * BM;
    const int ttx = t & 31;   // n microtile: 4 cols at ttx*4
    const int tty = t >> 5;   // m microtile: 8 rows at tty*8

    unsigned long long acc[4][4];   // [m-pair][n], each holds (m_even, m_odd)
    #pragma unroll
    for (int i = 0; i < 4; i++)
        #pragma unroll
        for (int j = 0; j < 4; j++) acc[i][j] = 0ULL;

    const int aRow = t >> 2;          // m within tile (0..63)
    const int aCol = (t & 3) * 4;     // k within tile
    const int bRow = t >> 4;          // k within tile (0..15)
    const int bCol = (t & 15) * 8;    // n within tile

    for (int k0 = 0; k0 < K; k0 += BK) {
        float4 av = *(const float4*)(&W[(size_t)(m0 + aRow) * K + k0 + aCol]);
        As[aCol + 0][aRow] = av.x;
        As[aCol + 1][aRow] = av.y;
        As[aCol + 2][aRow] = av.z;
        As[aCol + 3][aRow] = av.w;

        const float* xp = &X[(size_t)(k0 + bRow) * NTOT + n0 + bCol];
        float4 b0v = *(const float4*)(xp);
        float4 b1v = *(const float4*)(xp + 4);
        *(float4*)(&Bs[bRow][bCol])     = b0v;
        *(float4*)(&Bs[bRow][bCol + 4]) = b1v;
        __syncthreads();

        #pragma unroll
        for (int k = 0; k < BK; k++) {
            const ulonglong2* arow = (const ulonglong2*)(&As[k][0]);
            ulonglong2 a01 = arow[tty * 2];       // m pairs (0,1),(2,3)
            ulonglong2 a23 = arow[tty * 2 + 1];   // m pairs (4,5),(6,7)
            unsigned long long ap[4] = {a01.x, a01.y, a23.x, a23.y};

            float4 bv = *(const float4*)(&Bs[k][ttx * 4]);
            unsigned long long bd[4];
            DUP_F32X2(bd[0], bv.x);
            DUP_F32X2(bd[1], bv.y);
            DUP_F32X2(bd[2], bv.z);
            DUP_F32X2(bd[3], bv.w);

            #pragma unroll
            for (int i = 0; i < 4; i++)
                #pragma unroll
                for (int j = 0; j < 4; j++)
                    FMA_F32X2(acc[i][j], ap[i], bd[j]);
        }
        __syncthreads();
    }

    #pragma unroll
    for (int i = 0; i < 4; i++) {
        float lo[4], hi[4];
        #pragma unroll
        for (int j = 0; j < 4; j++) UNPACK_F32X2(lo[j], hi[j], acc[i][j]);
        const int mA = m0 + tty * 8 + i * 2;
        const int n  = n0 + ttx * 4;
        const float bA = __ldg(bias + mA), bB = __ldg(bias + mA + 1);
        float4 vA = make_float4(lo[0] + bA, lo[1] + bA, lo[2] + bA, lo[3] + bA);
        float4 vB = make_float4(hi[0] + bB, hi[1] + bB, hi[2] + bB, hi[3] + bB);
        *(float4*)(&g_Z[(size_t)mA * NTOT + n])       = vA;
        *(float4*)(&g_Z[(size_t)(mA + 1) * NTOT + n]) = vB;
    }
}

// ---------------- kernel 3: per-channel mean / rstd over g_Z ----------------
__global__ __launch_bounds__(256) void stats_kernel() {
    __shared__ float ssum[256];
    __shared__ float ssq[256];
    const int c = blockIdx.x;
    const int tid = threadIdx.x;
    const float* row = g_Z + (size_t)c * NTOT;
    float s = 0.0f, q = 0.0f;
    #pragma unroll 4
    for (int i = tid; i < NTOT; i += 256) {
        float v = row[i];
        s += v;
        q = fmaf(v, v, q);
    }
    ssum[tid] = s; ssq[tid] = q;
    __syncthreads();
    for (int off = 128; off > 0; off >>= 1) {
        if (tid < off) { ssum[tid] += ssum[tid + off]; ssq[tid] += ssq[tid + off]; }
        __syncthreads();
    }
    if (tid == 0) {
        float m = ssum[0] * (1.0f / NTOT);
        float var = ssq[0] * (1.0f / NTOT) - m * m;
        g_mean[c] = m;
        g_rstd[c] = rsqrtf(var + BN_EPS);
    }
}

// ---------------- kernel 4: BN + GELU elementwise (vectorized x4) ----------------
__global__ __launch_bounds__(256) void bn_gelu_kernel(
    const float* __restrict__ g, const float* __restrict__ bt, float* __restrict__ A)
{
    const int idx4 = blockIdx.x * blockDim.x + threadIdx.x;     // over OUTCH*NTOT/4
    const int c = idx4 >> 13;                                   // (idx4*4) / 32768
    float4 z = ((const float4*)g_Z)[idx4];
    const float m = g_mean[c];
    const float r = g_rstd[c] * __ldg(g + c);
    const float b = __ldg(bt + c);
    float4 o;
    o.x = gelu_exact((z.x - m) * r + b);
    o.y = gelu_exact((z.y - m) * r + b);
    o.z = gelu_exact((z.z - m) * r + b);
    o.w = gelu_exact((z.w - m) * r + b);
    ((float4*)A)[idx4] = o;
}

// ---------------- kernel 5: BN3 + residual + GELU + transpose to (B,N,C) ----------------
__global__ __launch_bounds__(256) void final_kernel(
    const float* __restrict__ g, const float* __restrict__ bt, float* __restrict__ out)
{
    __shared__ float tile[32][33];
    const int n0 = blockIdx.x * 32;
    const int c0 = blockIdx.y * 32;
    const int tx = threadIdx.x;   // 0..31
    const int ty = threadIdx.y;   // 0..7

    #pragma unroll
    for (int i = ty; i < 32; i += 8) {
        const int c = c0 + i;
        const int n = n0 + tx;
        const size_t idx = (size_t)c * NTOT + n;
        float x = (g_Z[idx] - g_mean[c]) * g_rstd[c] * __ldg(g + c) + __ldg(bt + c);
        x += g_A1[idx];
        tile[i][tx] = gelu_exact(x);
    }
    __syncthreads();
    #pragma unroll
    for (int i = ty; i < 32; i += 8) {
        const int n = n0 + i;
        const int c = c0 + tx;
        out[(size_t)n * OUTCH + c] = tile[tx][i];
    }
}

// ---------------- launch ----------------
extern "C" void kernel_launch(void* const* d_in, const int* in_sizes, int n_in,
                              void* d_out, int out_size) {
    const float* xyz1    = (const float*)d_in[0];
    const float* xyz2    = (const float*)d_in[1];
    const float* points1 = (const float*)d_in[2];
    const float* points2 = (const float*)d_in[3];
    const float* W_fuse  = (const float*)d_in[4];
    const float* b_fuse  = (const float*)d_in[5];
    const float* g_fuse  = (const float*)d_in[6];
    const float* bt_fuse = (const float*)d_in[7];
    const float* W1      = (const float*)d_in[8];
    const float* b1      = (const float*)d_in[9];
    const float* g1      = (const float*)d_in[10];
    const float* bt1     = (const float*)d_in[11];
    const float* W2      = (const float*)d_in[12];
    const float* b2      = (const float*)d_in[13];
    const float* g2      = (const float*)d_in[14];
    const float* bt2     = (const float*)d_in[15];
    float* out = (float*)d_out;

    float *pXin = nullptr, *pA1 = nullptr, *pA2 = nullptr;
    cudaGetSymbolAddress((void**)&pXin, g_Xin);
    cudaGetSymbolAddress((void**)&pA1, g_A1);
    cudaGetSymbolAddress((void**)&pA2, g_A2);

    // 1) 3-NN interpolation + concat
    interp_kernel<<<dim3(NPTS / 256, BATCH), 256>>>(xyz1, xyz2, points1, points2);

    const dim3 gemm_grid(NTOT / 128, OUTCH / 64);
    const int bn_blocks = (OUTCH * NTOT / 4) / 256;

    // layer "fuse": Z = W_fuse @ Xin + b; A1 = gelu(bn(Z))
    gemm_bias_kernel<INCH><<<gemm_grid, 256>>>(W_fuse, b_fuse, pXin);
    stats_kernel<<<OUTCH, 256>>>();
    bn_gelu_kernel<<<bn_blocks, 256>>>(g_fuse, bt_fuse, pA1);

    // layer 1: Z = W1 @ A1 + b; A2 = gelu(bn(Z))
    gemm_bias_kernel<OUTCH><<<gemm_grid, 256>>>(W1, b1, pA1);
    stats_kernel<<<OUTCH, 256>>>();
    bn_gelu_kernel<<<bn_blocks, 256>>>(g1, bt1, pA2);

    // layer 2: Z = W2 @ A2 + b; out = transpose(gelu(bn(Z) + A1))
    gemm_bias_kernel<OUTCH><<<gemm_grid, 256>>>(W2, b2, pA2);
    stats_kernel<<<OUTCH, 256>>>();
    final_kernel<<<dim3(NTOT / 32, OUTCH / 32), dim3(32, 8)>>>(g2, bt2, out);
}

// round 3
// speedup vs baseline: 1.1354x; 1.1354x over previous
#include <cuda_runtime.h>
#include <cuda_bf16.h>
#include <math.h>
#include <stdint.h>

#define BATCH 8
#define NPTS 4096
#define SPTS 1024
#define D1 128
#define D2 256
#define INCH 384
#define OUTCH 256
#define NTOT (BATCH * NPTS)   // 32768
#define BN_EPS 1e-5f

// ---------------- scratch (device globals; no allocs allowed) ----------------
__device__ __align__(256) __nv_bfloat16 g_Xh[(size_t)NTOT * INCH];
__device__ __align__(256) __nv_bfloat16 g_Xl[(size_t)NTOT * INCH];
__device__ __align__(256) __nv_bfloat16 g_A1h[(size_t)NTOT * OUTCH];
__device__ __align__(256) __nv_bfloat16 g_A1l[(size_t)NTOT * OUTCH];
__device__ __align__(256) __nv_bfloat16 g_A2h[(size_t)NTOT * OUTCH];
__device__ __align__(256) __nv_bfloat16 g_A2l[(size_t)NTOT * OUTCH];
__device__ __align__(256) float g_Z[(size_t)NTOT * OUTCH];   // sample-major [32768][256]
__device__ __align__(256) __nv_bfloat16 g_Wh[OUTCH * INCH];
__device__ __align__(256) __nv_bfloat16 g_Wl[OUTCH * INCH];
__device__ float g_w3[NTOT * 3];
__device__ int   g_i3[NTOT * 3];
__device__ float g_ps[256 * OUTCH];
__device__ float g_pq[256 * OUTCH];
__device__ float g_scale[OUTCH];
__device__ float g_shift[OUTCH];

// ---------------- helpers ----------------
__device__ __forceinline__ uint32_t smem_to_u32(const void* p) {
    uint32_t a;
    asm("{ .reg .u64 t; cvta.to.shared.u64 t, %1; cvt.u32.u64 %0, t; }" : "=r"(a) : "l"(p));
    return a;
}
#define SMZ(o) ((o) ^ (((o) >> 3) & 0x70))
#define CP16(dst, src) \
    asm volatile("cp.async.cg.shared.global [%0], [%1], 16;" :: "r"(dst), "l"(src) : "memory")

__device__ __forceinline__ void ldsm_x4(uint32_t& r0, uint32_t& r1, uint32_t& r2, uint32_t& r3,
                                        uint32_t addr) {
    asm volatile("ldmatrix.sync.aligned.m8n8.x4.shared.b16 {%0,%1,%2,%3}, [%4];"
                 : "=r"(r0), "=r"(r1), "=r"(r2), "=r"(r3) : "r"(addr));
}
__device__ __forceinline__ void mma_bf16(float& c0, float& c1, float& c2, float& c3,
                                         uint32_t a0, uint32_t a1, uint32_t a2, uint32_t a3,
                                         uint32_t b0, uint32_t b1) {
    asm volatile("mma.sync.aligned.m16n8k16.row.col.f32.bf16.bf16.f32 "
                 "{%0,%1,%2,%3}, {%4,%5,%6,%7}, {%8,%9}, {%0,%1,%2,%3};"
                 : "+f"(c0), "+f"(c1), "+f"(c2), "+f"(c3)
                 : "r"(a0), "r"(a1), "r"(a2), "r"(a3), "r"(b0), "r"(b1));
}

__device__ __forceinline__ float gelu_exact(float x) {
    return 0.5f * x * (1.0f + erff(x * 0.70710678118654752f));
}
__device__ __forceinline__ uint32_t pack_bf16(float a, float b) {
    __nv_bfloat162 t = __floats2bfloat162_rn(a, b);
    return *reinterpret_cast<uint32_t*>(&t);
}

// ---------------- kernel 1: per-sample top-3 neighbors + weights ----------------
__global__ __launch_bounds__(256) void topk_kernel(
    const float* __restrict__ xyz1, const float* __restrict__ xyz2)
{
    __shared__ float4 q[SPTS];
    const int b = blockIdx.y;
    const int n = blockIdx.x * blockDim.x + threadIdx.x;

    for (int s = threadIdx.x; s < SPTS; s += blockDim.x) {
        const float* p = xyz2 + ((size_t)b * SPTS + s) * 3;
        float x = p[0], y = p[1], z = p[2];
        q[s] = make_float4(x, y, z, x * x + y * y + z * z);
    }
    __syncthreads();

    const float* p = xyz1 + ((size_t)b * NPTS + n) * 3;
    float px = p[0], py = p[1], pz = p[2];
    float rn = px * px + py * py + pz * pz;

    float d0 = 3.4e38f, d1 = 3.4e38f, d2 = 3.4e38f;
    int i0 = 0, i1 = 0, i2 = 0;
    #pragma unroll 4
    for (int s = 0; s < SPTS; s++) {
        float4 qq = q[s];
        float d = rn - 2.0f * (px * qq.x + py * qq.y + pz * qq.z) + qq.w;
        if (d < d2) {
            if (d < d1) {
                if (d < d0) { d2 = d1; i2 = i1; d1 = d0; i1 = i0; d0 = d; i0 = s; }
                else        { d2 = d1; i2 = i1; d1 = d;  i1 = s; }
            } else          { d2 = d;  i2 = s; }
        }
    }
    float r0 = 1.0f / (d0 + 1e-8f);
    float r1 = 1.0f / (d1 + 1e-8f);
    float r2 = 1.0f / (d2 + 1e-8f);
    float rs = 1.0f / (r0 + r1 + r2);
    const int sample = b * NPTS + n;
    g_w3[sample * 3 + 0] = r0 * rs;
    g_w3[sample * 3 + 1] = r1 * rs;
    g_w3[sample * 3 + 2] = r2 * rs;
    g_i3[sample * 3 + 0] = i0;
    g_i3[sample * 3 + 1] = i1;
    g_i3[sample * 3 + 2] = i2;
}

// ---------------- kernel 2: build fused input in bf16 hi/lo, sample-major ----------------
__global__ __launch_bounds__(384) void build_input(
    const float* __restrict__ points1, const float* __restrict__ points2)
{
    __shared__ float w[3];
    __shared__ int id[3];
    const int n = blockIdx.x;
    if (threadIdx.x < 3) {
        w[threadIdx.x]  = g_w3[n * 3 + threadIdx.x];
        id[threadIdx.x] = g_i3[n * 3 + threadIdx.x];
    }
    __syncthreads();
    const int c = threadIdx.x;
    float v;
    if (c < D1) {
        v = __ldg(points1 + (size_t)n * D1 + c);
    } else {
        const int b = n >> 12;
        const int cc = c - D1;
        const float* base = points2 + (size_t)b * SPTS * D2 + cc;
        v = w[0] * __ldg(base + (size_t)id[0] * D2)
          + w[1] * __ldg(base + (size_t)id[1] * D2)
          + w[2] * __ldg(base + (size_t)id[2] * D2);
    }
    __nv_bfloat16 h = __float2bfloat16(v);
    __nv_bfloat16 l = __float2bfloat16(v - __bfloat162float(h));
    g_Xh[(size_t)n * INCH + c] = h;
    g_Xl[(size_t)n * INCH + c] = l;
}

// ---------------- kernel 3: weight split fp32 -> bf16 hi/lo ----------------
__global__ __launch_bounds__(256) void wsplit(const float* __restrict__ W, int n) {
    int i = blockIdx.x * 256 + threadIdx.x;
    if (i < n) {
        float w = W[i];
        __nv_bfloat16 h = __float2bfloat16(w);
        g_Wh[i] = h;
        g_Wl[i] = __float2bfloat16(w - __bfloat162float(h));
    }
}

// ---------------- GEMM via mma.sync: Z[sample][ch] = X @ W^T + bias ----------------
// CTA 128x128, BK=64, double-buffered cp.async, 3 compensation segments.
// SMEM layout per stage: A 16KB + B 16KB; stages at 0 and 32768; bias at 65536.
#define STAGE_SZ 32768
#define GEMM_SMEM (2 * STAGE_SZ + 512)

__device__ __forceinline__ void load_tile128(uint32_t dst, const __nv_bfloat16* src,
                                             int ldK, int row0, int k0, int tid) {
    #pragma unroll
    for (int j = 0; j < 4; j++) {
        int g = tid + j * 256;
        int r = g >> 3;
        int c16 = (g & 7) * 16;
        const char* s = (const char*)(src + (size_t)(row0 + r) * ldK + k0) + c16;
        CP16(dst + SMZ(r * 128 + c16), s);
    }
}

template <int K>
__global__ __launch_bounds__(256) void gemm_mma(
    const __nv_bfloat16* __restrict__ Xh, const __nv_bfloat16* __restrict__ Xl,
    const float* __restrict__ bias)
{
    constexpr int KC = K / 64;       // chunks per segment
    constexpr int NC = 3 * KC;       // total chunks (3 compensation segments)
    extern __shared__ char smem[];
    const uint32_t sb = smem_to_u32(smem);
    const int tid = threadIdx.x;
    const int wid = tid >> 5;
    const int lane = tid & 31;
    const int sample0 = blockIdx.x * 128;
    const int n0 = blockIdx.y * 128;

    const int mWarp = (wid & 1) * 64;
    const int nWarp = (wid >> 1) * 32;

    if (tid < 128) ((float*)(smem + 2 * STAGE_SZ))[tid] = bias[n0 + tid];

    const __nv_bfloat16* Aseg[3] = {Xh, Xl, Xh};
    const __nv_bfloat16* Bseg[3] = {g_Wh, g_Wh, g_Wl};

    // issue first two chunk loads
    #pragma unroll 1
    for (int i = 0; i < 2; i++) {
        const int seg = i / KC, kk = (i % KC) * 64;
        const uint32_t st = sb + i * STAGE_SZ;
        load_tile128(st,         Aseg[seg], K, sample0, kk, tid);
        load_tile128(st + 16384, Bseg[seg], K, n0,      kk, tid);
        asm volatile("cp.async.commit_group;" ::: "memory");
    }

    float acc[4][4][4];
    #pragma unroll
    for (int a = 0; a < 4; a++)
        #pragma unroll
        for (int b = 0; b < 4; b++)
            #pragma unroll
            for (int c = 0; c < 4; c++) acc[a][b][c] = 0.0f;

    // precomputed intra-tile ldmatrix offsets (swizzled per-lane)
    const int aRow = mWarp + (lane & 15);
    const int aColHalf = (lane >> 4) * 16;             // bytes
    const int bRow = nWarp + ((lane >> 4) << 3) + (lane & 7);
    const int bColHalf = ((lane >> 3) & 1) * 16;       // bytes

    for (int i = 0; i < NC; i++) {
        if (i + 1 < NC) asm volatile("cp.async.wait_group 1;" ::: "memory");
        else            asm volatile("cp.async.wait_group 0;" ::: "memory");
        __syncthreads();

        const uint32_t sA = sb + (i & 1) * STAGE_SZ;
        const uint32_t sB = sA + 16384;

        #pragma unroll
        for (int k16 = 0; k16 < 4; k16++) {
            uint32_t af[4][4];
            #pragma unroll
            for (int mb = 0; mb < 4; mb++) {
                uint32_t addr = sA + SMZ((aRow + mb * 16) * 128 + k16 * 32 + aColHalf);
                ldsm_x4(af[mb][0], af[mb][1], af[mb][2], af[mb][3], addr);
            }
            uint32_t bf[2][4];
            #pragma unroll
            for (int p = 0; p < 2; p++) {
                uint32_t addr = sB + SMZ((bRow + p * 16) * 128 + k16 * 32 + bColHalf);
                ldsm_x4(bf[p][0], bf[p][1], bf[p][2], bf[p][3], addr);
            }
            #pragma unroll
            for (int mb = 0; mb < 4; mb++)
                #pragma unroll
                for (int nb = 0; nb < 4; nb++) {
                    uint32_t b0 = bf[nb >> 1][(nb & 1) * 2];
                    uint32_t b1 = bf[nb >> 1][(nb & 1) * 2 + 1];
                    mma_bf16(acc[mb][nb][0], acc[mb][nb][1], acc[mb][nb][2], acc[mb][nb][3],
                             af[mb][0], af[mb][1], af[mb][2], af[mb][3], b0, b1);
                }
        }
        __syncthreads();

        if (i + 2 < NC) {
            const int j = i + 2;
            const int seg = j / KC, kk = (j % KC) * 64;
            const uint32_t st = sb + (j & 1) * STAGE_SZ;
            load_tile128(st,         Aseg[seg], K, sample0, kk, tid);
            load_tile128(st + 16384, Bseg[seg], K, n0,      kk, tid);
            asm volatile("cp.async.commit_group;" ::: "memory");
        }
    }

    // epilogue: add bias, write fp32 Z (sample-major)
    const float* sbias = (const float*)(smem + 2 * STAGE_SZ);
    const int rr = lane >> 2;            // 0..7
    const int cc = (lane & 3) * 2;       // 0..6
    #pragma unroll
    for (int mb = 0; mb < 4; mb++) {
        #pragma unroll
        for (int nb = 0; nb < 4; nb++) {
            const int col = nWarp + nb * 8 + cc;       // within 128-col tile
            const float b0 = sbias[col], b1 = sbias[col + 1];
            const int row0 = sample0 + mWarp + mb * 16 + rr;
            float2 v0 = make_float2(acc[mb][nb][0] + b0, acc[mb][nb][1] + b1);
            float2 v1 = make_float2(acc[mb][nb][2] + b0, acc[mb][nb][3] + b1);
            *(float2*)(g_Z + (size_t)row0 * OUTCH + n0 + col)       = v0;
            *(float2*)(g_Z + (size_t)(row0 + 8) * OUTCH + n0 + col) = v1;
        }
    }
}

// ---------------- stats: per-channel partial sums over sample-major Z ----------------
__global__ __launch_bounds__(256) void stats1() {
    const int c = threadIdx.x;
    const int r0 = blockIdx.x * 128;
    float s = 0.0f, q = 0.0f;
    const float* base = g_Z + (size_t)r0 * OUTCH + c;
    #pragma unroll 4
    for (int r = 0; r < 128; r++) {
        float v = base[(size_t)r * OUTCH];
        s += v;
        q = fmaf(v, v, q);
    }
    g_ps[blockIdx.x * OUTCH + c] = s;
    g_pq[blockIdx.x * OUTCH + c] = q;
}

__global__ __launch_bounds__(256) void stats2(
    const float* __restrict__ gamma, const float* __restrict__ beta)
{
    const int c = threadIdx.x;
    float s = 0.0f, q = 0.0f;
    #pragma unroll 4
    for (int p = 0; p < 256; p++) {
        s += g_ps[p * OUTCH + c];
        q += g_pq[p * OUTCH + c];
    }
    float m = s * (1.0f / NTOT);
    float var = q * (1.0f / NTOT) - m * m;
    float r = rsqrtf(var + BN_EPS);
    float sc = r * gamma[c];
    g_scale[c] = sc;
    g_shift[c] = beta[c] - m * sc;
}

// ---------------- BN + GELU -> bf16 hi/lo activation ----------------
__global__ __launch_bounds__(256) void bn_act(
    __nv_bfloat16* __restrict__ Ah, __nv_bfloat16* __restrict__ Al)
{
    const int idx4 = blockIdx.x * 256 + threadIdx.x;
    const int c4 = (idx4 & 63) * 4;
    float4 z = ((const float4*)g_Z)[idx4];
    float4 sc = *(const float4*)(g_scale + c4);
    float4 sh = *(const float4*)(g_shift + c4);
    float a0 = gelu_exact(fmaf(z.x, sc.x, sh.x));
    float a1 = gelu_exact(fmaf(z.y, sc.y, sh.y));
    float a2 = gelu_exact(fmaf(z.z, sc.z, sh.z));
    float a3 = gelu_exact(fmaf(z.w, sc.w, sh.w));
    uint2 hv, lv;
    hv.x = pack_bf16(a0, a1);
    hv.y = pack_bf16(a2, a3);
    float h0 = __bfloat162float(__float2bfloat16(a0));
    float h1 = __bfloat162float(__float2bfloat16(a1));
    float h2 = __bfloat162float(__float2bfloat16(a2));
    float h3 = __bfloat162float(__float2bfloat16(a3));
    lv.x = pack_bf16(a0 - h0, a1 - h1);
    lv.y = pack_bf16(a2 - h2, a3 - h3);
    ((uint2*)Ah)[idx4] = hv;
    ((uint2*)Al)[idx4] = lv;
}

// ---------------- final: BN + residual + GELU -> out (sample-major already) ----------------
__global__ __launch_bounds__(256) void final_k(float* __restrict__ out) {
    const int idx4 = blockIdx.x * 256 + threadIdx.x;
    const int c4 = (idx4 & 63) * 4;
    float4 z = ((const float4*)g_Z)[idx4];
    float4 sc = *(const float4*)(g_scale + c4);
    float4 sh = *(const float4*)(g_shift + c4);
    uint2 hv = ((const uint2*)g_A1h)[idx4];
    uint2 lv = ((const uint2*)g_A1l)[idx4];
    __nv_bfloat162 h01 = *(__nv_bfloat162*)&hv.x;
    __nv_bfloat162 h23 = *(__nv_bfloat162*)&hv.y;
    __nv_bfloat162 l01 = *(__nv_bfloat162*)&lv.x;
    __nv_bfloat162 l23 = *(__nv_bfloat162*)&lv.y;
    float r0 = __bfloat162float(h01.x) + __bfloat162float(l01.x);
    float r1 = __bfloat162float(h01.y) + __bfloat162float(l01.y);
    float r2 = __bfloat162float(h23.x) + __bfloat162float(l23.x);
    float r3 = __bfloat162float(h23.y) + __bfloat162float(l23.y);
    float4 o;
    o.x = gelu_exact(fmaf(z.x, sc.x, sh.x) + r0);
    o.y = gelu_exact(fmaf(z.y, sc.y, sh.y) + r1);
    o.z = gelu_exact(fmaf(z.z, sc.z, sh.z) + r2);
    o.w = gelu_exact(fmaf(z.w, sc.w, sh.w) + r3);
    ((float4*)out)[idx4] = o;
}

// ---------------- launch ----------------
extern "C" void kernel_launch(void* const* d_in, const int* in_sizes, int n_in,
                              void* d_out, int out_size) {
    const float* xyz1    = (const float*)d_in[0];
    const float* xyz2    = (const float*)d_in[1];
    const float* points1 = (const float*)d_in[2];
    const float* points2 = (const float*)d_in[3];
    const float* W_fuse  = (const float*)d_in[4];
    const float* b_fuse  = (const float*)d_in[5];
    const float* g_fuse  = (const float*)d_in[6];
    const float* bt_fuse = (const float*)d_in[7];
    const float* W1      = (const float*)d_in[8];
    const float* b1      = (const float*)d_in[9];
    const float* g1      = (const float*)d_in[10];
    const float* bt1     = (const float*)d_in[11];
    const float* W2      = (const float*)d_in[12];
    const float* b2      = (const float*)d_in[13];
    const float* g2      = (const float*)d_in[14];
    const float* bt2     = (const float*)d_in[15];
    float* out = (float*)d_out;

    __nv_bfloat16 *pXh, *pXl, *pA1h, *pA1l, *pA2h, *pA2l;
    cudaGetSymbolAddress((void**)&pXh,  g_Xh);
    cudaGetSymbolAddress((void**)&pXl,  g_Xl);
    cudaGetSymbolAddress((void**)&pA1h, g_A1h);
    cudaGetSymbolAddress((void**)&pA1l, g_A1l);
    cudaGetSymbolAddress((void**)&pA2h, g_A2h);
    cudaGetSymbolAddress((void**)&pA2l, g_A2l);

    cudaFuncSetAttribute(gemm_mma<INCH>,  cudaFuncAttributeMaxDynamicSharedMemorySize, GEMM_SMEM);
    cudaFuncSetAttribute(gemm_mma<OUTCH>, cudaFuncAttributeMaxDynamicSharedMemorySize, GEMM_SMEM);

    const dim3 gemm_grid(NTOT / 128, OUTCH / 128);
    const int bn_blocks = (OUTCH * NTOT / 4) / 256;   // 8192

    topk_kernel<<<dim3(NPTS / 256, BATCH), 256>>>(xyz1, xyz2);
    build_input<<<NTOT, 384>>>(points1, points2);

    // layer fuse
    wsplit<<<(OUTCH * INCH + 255) / 256, 256>>>(W_fuse, OUTCH * INCH);
    gemm_mma<INCH><<<gemm_grid, 256, GEMM_SMEM>>>(pXh, pXl, b_fuse);
    stats1<<<256, 256>>>();
    stats2<<<1, 256>>>(g_fuse, bt_fuse);
    bn_act<<<bn_blocks, 256>>>(pA1h, pA1l);

    // layer 1
    wsplit<<<(OUTCH * OUTCH + 255) / 256, 256>>>(W1, OUTCH * OUTCH);
    gemm_mma<OUTCH><<<gemm_grid, 256, GEMM_SMEM>>>(pA1h, pA1l, b1);
    stats1<<<256, 256>>>();
    stats2<<<1, 256>>>(g1, bt1);
    bn_act<<<bn_blocks, 256>>>(pA2h, pA2l);

    // layer 2 + residual + output
    wsplit<<<(OUTCH * OUTCH + 255) / 256, 256>>>(W2, OUTCH * OUTCH);
    gemm_mma<OUTCH><<<gemm_grid, 256, GEMM_SMEM>>>(pA2h, pA2l, b2);
    stats1<<<256, 256>>>();
    stats2<<<1, 256>>>(g2, bt2);
    final_k<<<bn_blocks, 256>>>(out);
}

// round 4
// speedup vs baseline: 1.4670x; 1.2920x over previous
#include <cuda_runtime.h>
#include <cuda_bf16.h>
#include <math.h>
#include <stdint.h>

#define BATCH 8
#define NPTS 4096
#define SPTS 1024
#define D1 128
#define D2 256
#define INCH 384
#define OUTCH 256
#define NTOT (BATCH * NPTS)   // 32768
#define BN_EPS 1e-5f
#define WTOT (OUTCH * INCH + 2 * OUTCH * OUTCH)   // 229376

// ---------------- scratch (device globals; no allocs allowed) ----------------
__device__ __align__(256) __nv_bfloat16 g_Xh[(size_t)NTOT * INCH];
__device__ __align__(256) __nv_bfloat16 g_Xl[(size_t)NTOT * INCH];
__device__ __align__(256) __nv_bfloat16 g_A1h[(size_t)NTOT * OUTCH];
__device__ __align__(256) __nv_bfloat16 g_A1l[(size_t)NTOT * OUTCH];
__device__ __align__(256) __nv_bfloat16 g_A2h[(size_t)NTOT * OUTCH];
__device__ __align__(256) __nv_bfloat16 g_A2l[(size_t)NTOT * OUTCH];
__device__ __align__(256) float g_Z[(size_t)NTOT * OUTCH];   // sample-major [32768][256]
__device__ __align__(256) __nv_bfloat16 g_Wh[WTOT];
__device__ __align__(256) __nv_bfloat16 g_Wl[WTOT];
__device__ float g_w3[NTOT * 3];
__device__ int   g_i3[NTOT * 3];
__device__ float g_ps[64 * OUTCH];
__device__ float g_pq[64 * OUTCH];
__device__ float g_scale[OUTCH];
__device__ float g_shift[OUTCH];

// ---------------- helpers ----------------
__device__ __forceinline__ uint32_t smem_to_u32(const void* p) {
    uint32_t a;
    asm("{ .reg .u64 t; cvta.to.shared.u64 t, %1; cvt.u32.u64 %0, t; }" : "=r"(a) : "l"(p));
    return a;
}
#define SMZ(o) ((o) ^ (((o) >> 3) & 0x70))
#define CP16(dst, src) \
    asm volatile("cp.async.cg.shared.global [%0], [%1], 16;" :: "r"(dst), "l"(src) : "memory")

__device__ __forceinline__ void ldsm_x4(uint32_t& r0, uint32_t& r1, uint32_t& r2, uint32_t& r3,
                                        uint32_t addr) {
    asm volatile("ldmatrix.sync.aligned.m8n8.x4.shared.b16 {%0,%1,%2,%3}, [%4];"
                 : "=r"(r0), "=r"(r1), "=r"(r2), "=r"(r3) : "r"(addr));
}
__device__ __forceinline__ void mma_bf16(float& c0, float& c1, float& c2, float& c3,
                                         uint32_t a0, uint32_t a1, uint32_t a2, uint32_t a3,
                                         uint32_t b0, uint32_t b1) {
    asm volatile("mma.sync.aligned.m16n8k16.row.col.f32.bf16.bf16.f32 "
                 "{%0,%1,%2,%3}, {%4,%5,%6,%7}, {%8,%9}, {%0,%1,%2,%3};"
                 : "+f"(c0), "+f"(c1), "+f"(c2), "+f"(c3)
                 : "r"(a0), "r"(a1), "r"(a2), "r"(a3), "r"(b0), "r"(b1));
}

__device__ __forceinline__ float gelu_exact(float x) {
    return 0.5f * x * (1.0f + erff(x * 0.70710678118654752f));
}
__device__ __forceinline__ uint32_t pack_bf16(float a, float b) {
    __nv_bfloat162 t = __floats2bfloat162_rn(a, b);
    return *reinterpret_cast<uint32_t*>(&t);
}

// ---------------- kernel 1: per-sample top-3 neighbors + weights ----------------
__global__ __launch_bounds__(256) void topk_kernel(
    const float* __restrict__ xyz1, const float* __restrict__ xyz2)
{
    __shared__ float4 q[SPTS];
    const int b = blockIdx.y;
    const int n = blockIdx.x * blockDim.x + threadIdx.x;

    for (int s = threadIdx.x; s < SPTS; s += blockDim.x) {
        const float* p = xyz2 + ((size_t)b * SPTS + s) * 3;
        float x = p[0], y = p[1], z = p[2];
        q[s] = make_float4(x, y, z, x * x + y * y + z * z);
    }
    __syncthreads();

    const float* p = xyz1 + ((size_t)b * NPTS + n) * 3;
    float px = p[0], py = p[1], pz = p[2];
    float rn = px * px + py * py + pz * pz;

    float d0 = 3.4e38f, d1 = 3.4e38f, d2 = 3.4e38f;
    int i0 = 0, i1 = 0, i2 = 0;
    #pragma unroll 4
    for (int s = 0; s < SPTS; s++) {
        float4 qq = q[s];
        float d = rn - 2.0f * (px * qq.x + py * qq.y + pz * qq.z) + qq.w;
        if (d < d2) {
            if (d < d1) {
                if (d < d0) { d2 = d1; i2 = i1; d1 = d0; i1 = i0; d0 = d; i0 = s; }
                else        { d2 = d1; i2 = i1; d1 = d;  i1 = s; }
            } else          { d2 = d;  i2 = s; }
        }
    }
    float r0 = 1.0f / (d0 + 1e-8f);
    float r1 = 1.0f / (d1 + 1e-8f);
    float r2 = 1.0f / (d2 + 1e-8f);
    float rs = 1.0f / (r0 + r1 + r2);
    const int sample = b * NPTS + n;
    g_w3[sample * 3 + 0] = r0 * rs;
    g_w3[sample * 3 + 1] = r1 * rs;
    g_w3[sample * 3 + 2] = r2 * rs;
    g_i3[sample * 3 + 0] = i0;
    g_i3[sample * 3 + 1] = i1;
    g_i3[sample * 3 + 2] = i2;
}

// ---------------- kernel 2: build fused input in bf16 hi/lo, sample-major ----------------
__global__ __launch_bounds__(384) void build_input(
    const float* __restrict__ points1, const float* __restrict__ points2)
{
    __shared__ float w[3];
    __shared__ int id[3];
    const int n = blockIdx.x;
    if (threadIdx.x < 3) {
        w[threadIdx.x]  = g_w3[n * 3 + threadIdx.x];
        id[threadIdx.x] = g_i3[n * 3 + threadIdx.x];
    }
    __syncthreads();
    const int c = threadIdx.x;
    float v;
    if (c < D1) {
        v = __ldg(points1 + (size_t)n * D1 + c);
    } else {
        const int b = n >> 12;
        const int cc = c - D1;
        const float* base = points2 + (size_t)b * SPTS * D2 + cc;
        v = w[0] * __ldg(base + (size_t)id[0] * D2)
          + w[1] * __ldg(base + (size_t)id[1] * D2)
          + w[2] * __ldg(base + (size_t)id[2] * D2);
    }
    __nv_bfloat16 h = __float2bfloat16(v);
    __nv_bfloat16 l = __float2bfloat16(v - __bfloat162float(h));
    g_Xh[(size_t)n * INCH + c] = h;
    g_Xl[(size_t)n * INCH + c] = l;
}

// ---------------- kernel 3: all weights fp32 -> bf16 hi/lo in one pass ----------------
__global__ __launch_bounds__(256) void wsplit_all(
    const float* __restrict__ Wf, const float* __restrict__ W1, const float* __restrict__ W2)
{
    int i = blockIdx.x * 256 + threadIdx.x;
    if (i >= WTOT) return;
    float w;
    if (i < OUTCH * INCH)                     w = Wf[i];
    else if (i < OUTCH * INCH + OUTCH * OUTCH) w = W1[i - OUTCH * INCH];
    else                                       w = W2[i - OUTCH * INCH - OUTCH * OUTCH];
    __nv_bfloat16 h = __float2bfloat16(w);
    g_Wh[i] = h;
    g_Wl[i] = __float2bfloat16(w - __bfloat162float(h));
}

// ---------------- GEMM via mma.sync: Z[sample][ch] = X @ W^T + bias ----------------
// CTA 128x128, BK=64, 3-stage cp.async pipeline, 3 compensation segments.
#define STAGE_SZ 32768
#define NSTAGE 3
#define GEMM_SMEM (NSTAGE * STAGE_SZ + 512)

__device__ __forceinline__ void load_tile128(uint32_t dst, const __nv_bfloat16* src,
                                             int ldK, int row0, int k0, int tid) {
    #pragma unroll
    for (int j = 0; j < 4; j++) {
        int g = tid + j * 256;
        int r = g >> 3;
        int c16 = (g & 7) * 16;
        const char* s = (const char*)(src + (size_t)(row0 + r) * ldK + k0) + c16;
        CP16(dst + SMZ(r * 128 + c16), s);
    }
}

template <int K>
__global__ __launch_bounds__(256, 2) void gemm_mma(
    const __nv_bfloat16* __restrict__ Xh, const __nv_bfloat16* __restrict__ Xl,
    const float* __restrict__ bias, int woff)
{
    constexpr int KC = K / 64;       // chunks per segment
    constexpr int NC = 3 * KC;       // total chunks (3 compensation segments)
    extern __shared__ char smem[];
    const uint32_t sb = smem_to_u32(smem);
    const int tid = threadIdx.x;
    const int wid = tid >> 5;
    const int lane = tid & 31;
    const int sample0 = blockIdx.x * 128;
    const int n0 = blockIdx.y * 128;

    const int mWarp = (wid & 1) * 64;
    const int nWarp = (wid >> 1) * 32;

    if (tid < 128) ((float*)(smem + NSTAGE * STAGE_SZ))[tid] = bias[n0 + tid];

    const __nv_bfloat16* Wh = g_Wh + woff;
    const __nv_bfloat16* Wl = g_Wl + woff;
    const __nv_bfloat16* Aseg[3] = {Xh, Xl, Xh};
    const __nv_bfloat16* Bseg[3] = {Wh, Wh, Wl};

    // prologue: fill all 3 stages
    #pragma unroll
    for (int i = 0; i < NSTAGE; i++) {
        const int seg = i / KC, kk = (i % KC) * 64;
        const uint32_t st = sb + i * STAGE_SZ;
        load_tile128(st,         Aseg[seg], K, sample0, kk, tid);
        load_tile128(st + 16384, Bseg[seg], K, n0,      kk, tid);
        asm volatile("cp.async.commit_group;" ::: "memory");
    }

    float acc[4][4][4];
    #pragma unroll
    for (int a = 0; a < 4; a++)
        #pragma unroll
        for (int b = 0; b < 4; b++)
            #pragma unroll
            for (int c = 0; c < 4; c++) acc[a][b][c] = 0.0f;

    const int aRow = mWarp + (lane & 15);
    const int aColHalf = (lane >> 4) * 16;             // bytes
    const int bRow = nWarp + ((lane >> 4) << 3) + (lane & 7);
    const int bColHalf = ((lane >> 3) & 1) * 16;       // bytes

    int stage = 0;
    for (int i = 0; i < NC; i++) {
        if (i <= NC - 3)      asm volatile("cp.async.wait_group 2;" ::: "memory");
        else if (i == NC - 2) asm volatile("cp.async.wait_group 1;" ::: "memory");
        else                  asm volatile("cp.async.wait_group 0;" ::: "memory");
        __syncthreads();

        const uint32_t sA = sb + stage * STAGE_SZ;
        const uint32_t sB = sA + 16384;

        #pragma unroll
        for (int k16 = 0; k16 < 4; k16++) {
            uint32_t af[4][4];
            #pragma unroll
            for (int mb = 0; mb < 4; mb++) {
                uint32_t addr = sA + SMZ((aRow + mb * 16) * 128 + k16 * 32 + aColHalf);
                ldsm_x4(af[mb][0], af[mb][1], af[mb][2], af[mb][3], addr);
            }
            uint32_t bf[2][4];
            #pragma unroll
            for (int p = 0; p < 2; p++) {
                uint32_t addr = sB + SMZ((bRow + p * 16) * 128 + k16 * 32 + bColHalf);
                ldsm_x4(bf[p][0], bf[p][1], bf[p][2], bf[p][3], addr);
            }
            #pragma unroll
            for (int mb = 0; mb < 4; mb++)
                #pragma unroll
                for (int nb = 0; nb < 4; nb++) {
                    uint32_t b0 = bf[nb >> 1][(nb & 1) * 2];
                    uint32_t b1 = bf[nb >> 1][(nb & 1) * 2 + 1];
                    mma_bf16(acc[mb][nb][0], acc[mb][nb][1], acc[mb][nb][2], acc[mb][nb][3],
                             af[mb][0], af[mb][1], af[mb][2], af[mb][3], b0, b1);
                }
        }
        __syncthreads();

        if (i + NSTAGE < NC) {
            const int j = i + NSTAGE;
            const int seg = j / KC, kk = (j % KC) * 64;
            const uint32_t st = sb + stage * STAGE_SZ;   // (i+3)%3 == i%3
            load_tile128(st,         Aseg[seg], K, sample0, kk, tid);
            load_tile128(st + 16384, Bseg[seg], K, n0,      kk, tid);
            asm volatile("cp.async.commit_group;" ::: "memory");
        }
        stage = (stage + 1 == NSTAGE) ? 0 : stage + 1;
    }

    // epilogue: add bias, write fp32 Z (sample-major)
    const float* sbias = (const float*)(smem + NSTAGE * STAGE_SZ);
    const int rr = lane >> 2;            // 0..7
    const int cc = (lane & 3) * 2;       // 0..6
    #pragma unroll
    for (int mb = 0; mb < 4; mb++) {
        #pragma unroll
        for (int nb = 0; nb < 4; nb++) {
            const int col = nWarp + nb * 8 + cc;       // within 128-col tile
            const float b0 = sbias[col], b1 = sbias[col + 1];
            const int row0 = sample0 + mWarp + mb * 16 + rr;
            float2 v0 = make_float2(acc[mb][nb][0] + b0, acc[mb][nb][1] + b1);
            float2 v1 = make_float2(acc[mb][nb][2] + b0, acc[mb][nb][3] + b1);
            *(float2*)(g_Z + (size_t)row0 * OUTCH + n0 + col)       = v0;
            *(float2*)(g_Z + (size_t)(row0 + 8) * OUTCH + n0 + col) = v1;
        }
    }
}

// ---------------- stats: per-channel partial sums over sample-major Z ----------------
__global__ __launch_bounds__(256) void stats1() {
    const int c = threadIdx.x;
    const int r0 = blockIdx.x * 512;
    float s = 0.0f, q = 0.0f;
    const float* base = g_Z + (size_t)r0 * OUTCH + c;
    #pragma unroll 4
    for (int r = 0; r < 512; r++) {
        float v = base[(size_t)r * OUTCH];
        s += v;
        q = fmaf(v, v, q);
    }
    g_ps[blockIdx.x * OUTCH + c] = s;
    g_pq[blockIdx.x * OUTCH + c] = q;
}

__global__ __launch_bounds__(256) void stats2(
    const float* __restrict__ gamma, const float* __restrict__ beta)
{
    const int c = threadIdx.x;
    float s = 0.0f, q = 0.0f;
    #pragma unroll
    for (int p = 0; p < 64; p++) {
        s += g_ps[p * OUTCH + c];
        q += g_pq[p * OUTCH + c];
    }
    float m = s * (1.0f / NTOT);
    float var = q * (1.0f / NTOT) - m * m;
    float r = rsqrtf(var + BN_EPS);
    float sc = r * gamma[c];
    g_scale[c] = sc;
    g_shift[c] = beta[c] - m * sc;
}

// ---------------- BN + GELU -> bf16 hi/lo activation ----------------
__global__ __launch_bounds__(256) void bn_act(
    __nv_bfloat16* __restrict__ Ah, __nv_bfloat16* __restrict__ Al)
{
    const int idx4 = blockIdx.x * 256 + threadIdx.x;
    const int c4 = (idx4 & 63) * 4;
    float4 z = ((const float4*)g_Z)[idx4];
    float4 sc = *(const float4*)(g_scale + c4);
    float4 sh = *(const float4*)(g_shift + c4);
    float a0 = gelu_exact(fmaf(z.x, sc.x, sh.x));
    float a1 = gelu_exact(fmaf(z.y, sc.y, sh.y));
    float a2 = gelu_exact(fmaf(z.z, sc.z, sh.z));
    float a3 = gelu_exact(fmaf(z.w, sc.w, sh.w));
    uint2 hv, lv;
    hv.x = pack_bf16(a0, a1);
    hv.y = pack_bf16(a2, a3);
    float h0 = __bfloat162float(__float2bfloat16(a0));
    float h1 = __bfloat162float(__float2bfloat16(a1));
    float h2 = __bfloat162float(__float2bfloat16(a2));
    float h3 = __bfloat162float(__float2bfloat16(a3));
    lv.x = pack_bf16(a0 - h0, a1 - h1);
    lv.y = pack_bf16(a2 - h2, a3 - h3);
    ((uint2*)Ah)[idx4] = hv;
    ((uint2*)Al)[idx4] = lv;
}

// ---------------- final: BN + residual + GELU -> out (sample-major already) ----------------
__global__ __launch_bounds__(256) void final_k(float* __restrict__ out) {
    const int idx4 = blockIdx.x * 256 + threadIdx.x;
    const int c4 = (idx4 & 63) * 4;
    float4 z = ((const float4*)g_Z)[idx4];
    float4 sc = *(const float4*)(g_scale + c4);
    float4 sh = *(const float4*)(g_shift + c4);
    uint2 hv = ((const uint2*)g_A1h)[idx4];
    uint2 lv = ((const uint2*)g_A1l)[idx4];
    __nv_bfloat162 h01 = *(__nv_bfloat162*)&hv.x;
    __nv_bfloat162 h23 = *(__nv_bfloat162*)&hv.y;
    __nv_bfloat162 l01 = *(__nv_bfloat162*)&lv.x;
    __nv_bfloat162 l23 = *(__nv_bfloat162*)&lv.y;
    float r0 = __bfloat162float(h01.x) + __bfloat162float(l01.x);
    float r1 = __bfloat162float(h01.y) + __bfloat162float(l01.y);
    float r2 = __bfloat162float(h23.x) + __bfloat162float(l23.x);
    float r3 = __bfloat162float(h23.y) + __bfloat162float(l23.y);
    float4 o;
    o.x = gelu_exact(fmaf(z.x, sc.x, sh.x) + r0);
    o.y = gelu_exact(fmaf(z.y, sc.y, sh.y) + r1);
    o.z = gelu_exact(fmaf(z.z, sc.z, sh.z) + r2);
    o.w = gelu_exact(fmaf(z.w, sc.w, sh.w) + r3);
    ((float4*)out)[idx4] = o;
}

// ---------------- launch ----------------
extern "C" void kernel_launch(void* const* d_in, const int* in_sizes, int n_in,
                              void* d_out, int out_size) {
    const float* xyz1    = (const float*)d_in[0];
    const float* xyz2    = (const float*)d_in[1];
    const float* points1 = (const float*)d_in[2];
    const float* points2 = (const float*)d_in[3];
    const float* W_fuse  = (const float*)d_in[4];
    const float* b_fuse  = (const float*)d_in[5];
    const float* g_fuse  = (const float*)d_in[6];
    const float* bt_fuse = (const float*)d_in[7];
    const float* W1      = (const float*)d_in[8];
    const float* b1      = (const float*)d_in[9];
    const float* g1      = (const float*)d_in[10];
    const float* bt1     = (const float*)d_in[11];
    const float* W2      = (const float*)d_in[12];
    const float* b2      = (const float*)d_in[13];
    const float* g2      = (const float*)d_in[14];
    const float* bt2     = (const float*)d_in[15];
    float* out = (float*)d_out;

    __nv_bfloat16 *pXh, *pXl, *pA1h, *pA1l, *pA2h, *pA2l;
    cudaGetSymbolAddress((void**)&pXh,  g_Xh);
    cudaGetSymbolAddress((void**)&pXl,  g_Xl);
    cudaGetSymbolAddress((void**)&pA1h, g_A1h);
    cudaGetSymbolAddress((void**)&pA1l, g_A1l);
    cudaGetSymbolAddress((void**)&pA2h, g_A2h);
    cudaGetSymbolAddress((void**)&pA2l, g_A2l);

    cudaFuncSetAttribute(gemm_mma<INCH>,  cudaFuncAttributeMaxDynamicSharedMemorySize, GEMM_SMEM);
    cudaFuncSetAttribute(gemm_mma<OUTCH>, cudaFuncAttributeMaxDynamicSharedMemorySize, GEMM_SMEM);

    const dim3 gemm_grid(NTOT / 128, OUTCH / 128);
    const int bn_blocks = (OUTCH * NTOT / 4) / 256;   // 8192

    wsplit_all<<<(WTOT + 255) / 256, 256>>>(W_fuse, W1, W2);
    topk_kernel<<<dim3(NPTS / 256, BATCH), 256>>>(xyz1, xyz2);
    build_input<<<NTOT, 384>>>(points1, points2);

    const int woff_f = 0;
    const int woff_1 = OUTCH * INCH;
    const int woff_2 = OUTCH * INCH + OUTCH * OUTCH;

    // layer fuse
    gemm_mma<INCH><<<gemm_grid, 256, GEMM_SMEM>>>(pXh, pXl, b_fuse, woff_f);
    stats1<<<64, 256>>>();
    stats2<<<1, 256>>>(g_fuse, bt_fuse);
    bn_act<<<bn_blocks, 256>>>(pA1h, pA1l);

    // layer 1
    gemm_mma<OUTCH><<<gemm_grid, 256, GEMM_SMEM>>>(pA1h, pA1l, b1, woff_1);
    stats1<<<64, 256>>>();
    stats2<<<1, 256>>>(g1, bt1);
    bn_act<<<bn_blocks, 256>>>(pA2h, pA2l);

    // layer 2 + residual + output
    gemm_mma<OUTCH><<<gemm_grid, 256, GEMM_SMEM>>>(pA2h, pA2l, b2, woff_2);
    stats1<<<64, 256>>>();
    stats2<<<1, 256>>>(g2, bt2);
    final_k<<<bn_blocks, 256>>>(out);
}